// round 3
// baseline (speedup 1.0000x reference)
#include <cuda_runtime.h>
#include <cuda_bf16.h>

#define N_IN       16
#define FANIN      16
#define N_NODES    512
#define N_OUT      64
#define BATCH      32768
#define NPAIRS     (BATCH / 2)          // 16384 packed f32x2 lanes
#define CHAINS     2                    // independent chains per thread (ILP)
#define OUT_START  (N_NODES - N_OUT)    // node 448

#define THREADS    64
#define GRID       (NPAIRS / CHAINS / THREADS)   // 128 CTAs

using u64 = unsigned long long;

// ---- packed f32x2 helpers (sm_10x) ----
__device__ __forceinline__ u64 pack2(float lo, float hi) {
    u64 r; asm("mov.b64 %0, {%1, %2};" : "=l"(r) : "f"(lo), "f"(hi)); return r;
}
__device__ __forceinline__ void unpack2(u64 v, float& lo, float& hi) {
    asm("mov.b64 {%0, %1}, %2;" : "=f"(lo), "=f"(hi) : "l"(v));
}
__device__ __forceinline__ u64 fma2(u64 a, u64 b, u64 c) {
    u64 d; asm("fma.rn.f32x2 %0, %1, %2, %3;" : "=l"(d) : "l"(a), "l"(b), "l"(c)); return d;
}
__device__ __forceinline__ u64 mul2(u64 a, u64 b) {
    u64 d; asm("mul.rn.f32x2 %0, %1, %2;" : "=l"(d) : "l"(a), "l"(b)); return d;
}
__device__ __forceinline__ u64 add2(u64 a, u64 b) {
    u64 d; asm("add.rn.f32x2 %0, %1, %2;" : "=l"(d) : "l"(a), "l"(b)); return d;
}
__device__ __forceinline__ float tanh_approx(float x) {
    float y; asm("tanh.approx.f32 %0, %1;" : "=f"(y) : "f"(x)); return y;
}

// Dynamic smem layout (u64 units):
//   [0, 8192)        : packed resp-folded weights {w',w'}  (64 KB)
//   [8192, 8704)     : packed bias {b,b} per node           (4 KB)
//   [8704, 8768)     : packed resp {r,r} for output nodes   (0.5 KB)
#define SMEM_W   0
#define SMEM_B   (N_NODES * FANIN)
#define SMEM_R   (SMEM_B + N_NODES)
#define SMEM_U64 (SMEM_R + N_OUT)

__global__ void __launch_bounds__(THREADS, 1)
neat_forward_ilp2(const float* __restrict__ x,
                  const float* __restrict__ w,      // [512][16]
                  const float* __restrict__ bias,   // [512]
                  const float* __restrict__ resp,   // [512]
                  float*       __restrict__ out)    // [BATCH][64]
{
    extern __shared__ __align__(16) u64 sh[];
    const int tid = threadIdx.x;

    // Fold each source node's response into the consumer weight:
    //   w'[i][t] = w[i][t] * resp[src-16]   (src = i + t; identity if src is an input)
    // The register window then carries raw tanh values; resp is applied only at
    // output-store time (off the serial recurrence path).
    for (int i = tid; i < N_NODES * FANIN; i += THREADS) {
        const int node = i >> 4, t = i & 15;
        const int g = node + t;                       // global source index
        const float scale = (g >= N_IN) ? resp[g - N_IN] : 1.0f;
        const float wv = w[i] * scale;
        sh[SMEM_W + i] = pack2(wv, wv);
    }
    for (int i = tid; i < N_NODES; i += THREADS) {
        const float bv = bias[i];
        sh[SMEM_B + i] = pack2(bv, bv);
    }
    for (int i = tid; i < N_OUT; i += THREADS) {
        const float rv = resp[OUT_START + i];
        sh[SMEM_R + i] = pack2(rv, rv);
    }
    __syncthreads();

    // Chain c of this thread handles the packed pair p = pbase + c*(NPAIRS/2),
    // i.e. batch elements (p, p + NPAIRS). All accesses coalesced.
    const int pbase = blockIdx.x * THREADS + tid;

    u64 v2[CHAINS][16];   // circular window per chain: v2[c][g & 15] = raw value at global g
    int pidx[CHAINS];
    #pragma unroll
    for (int c = 0; c < CHAINS; c++) {
        const int p = pbase + c * (NPAIRS / 2);
        pidx[c] = p;
        const float4* x0 = (const float4*)(x + (size_t)p * N_IN);
        const float4* x1 = (const float4*)(x + (size_t)(p + NPAIRS) * N_IN);
        #pragma unroll
        for (int q = 0; q < 4; q++) {
            float4 a = x0[q], b = x1[q];
            v2[c][4*q + 0] = pack2(a.x, b.x);
            v2[c][4*q + 1] = pack2(a.y, b.y);
            v2[c][4*q + 2] = pack2(a.z, b.z);
            v2[c][4*q + 3] = pack2(a.w, b.w);
        }
    }

    #pragma unroll 1
    for (int g = 0; g < N_NODES / 16; g++) {
        #pragma unroll
        for (int j = 0; j < 16; j++) {
            const int node = g * 16 + j;
            // 16 packed weights, loaded ONCE, shared by both chains (8x LDS.128).
            const ulonglong2* wv = (const ulonglong2*)(sh + SMEM_W + node * FANIN);
            const ulonglong2 q0 = wv[0], q1 = wv[1], q2 = wv[2], q3 = wv[3];
            const ulonglong2 q4 = wv[4], q5 = wv[5], q6 = wv[6], q7 = wv[7];
            const u64 b2 = sh[SMEM_B + node];

            u64 res[CHAINS];
            #pragma unroll
            for (int c = 0; c < CHAINS; c++) {
                // Bias folded into a0's first FMA. Newest tap (t=15, the value
                // produced by node-1) enters as the LAST fma of a3, and a3 joins
                // the add tree last — minimal serial path.
                u64 a0 = fma2(v2[c][(j + 0)  & 15], q0.x, b2);
                u64 a1 = mul2(v2[c][(j + 1)  & 15], q0.y);
                u64 a2 = mul2(v2[c][(j + 2)  & 15], q1.x);
                u64 a3 = mul2(v2[c][(j + 3)  & 15], q1.y);
                a0 = fma2(v2[c][(j + 4)  & 15], q2.x, a0);
                a1 = fma2(v2[c][(j + 5)  & 15], q2.y, a1);
                a2 = fma2(v2[c][(j + 6)  & 15], q3.x, a2);
                a3 = fma2(v2[c][(j + 7)  & 15], q3.y, a3);
                a0 = fma2(v2[c][(j + 8)  & 15], q4.x, a0);
                a1 = fma2(v2[c][(j + 9)  & 15], q4.y, a1);
                a2 = fma2(v2[c][(j + 10) & 15], q5.x, a2);
                a3 = fma2(v2[c][(j + 11) & 15], q5.y, a3);
                a0 = fma2(v2[c][(j + 12) & 15], q6.x, a0);
                a1 = fma2(v2[c][(j + 13) & 15], q6.y, a1);
                a2 = fma2(v2[c][(j + 14) & 15], q7.x, a2);
                a3 = fma2(v2[c][(j + 15) & 15], q7.y, a3);   // newest, last

                const u64 s   = add2(a0, a1);
                const u64 u_  = add2(s, a2);
                const u64 agg = add2(u_, a3);                // newest joins last

                float lo, hi;
                unpack2(agg, lo, hi);
                res[c] = pack2(tanh_approx(lo), tanh_approx(hi));
                v2[c][j] = res[c];
            }

            if (g >= OUT_START / 16) {
                const int o = node - OUT_START;
                const u64 r2 = sh[SMEM_R + o];
                #pragma unroll
                for (int c = 0; c < CHAINS; c++) {
                    float r0, r1;
                    unpack2(mul2(res[c], r2), r0, r1);       // apply response here
                    out[(size_t)pidx[c] * N_OUT + o]            = r0;
                    out[(size_t)(pidx[c] + NPAIRS) * N_OUT + o] = r1;
                }
            }
        }
    }
}

extern "C" void kernel_launch(void* const* d_in, const int* in_sizes, int n_in,
                              void* d_out, int out_size) {
    const float* x    = (const float*)d_in[0];   // [BATCH, 16]
    const float* w    = (const float*)d_in[1];   // [512, 16]
    const float* bias = (const float*)d_in[2];   // [512]
    const float* resp = (const float*)d_in[3];   // [512]
    // d_in[4] (src_idx) is the fixed sliding-window topology; baked into indexing.
    float* out = (float*)d_out;                  // [BATCH, 64]

    const int smem_bytes = SMEM_U64 * (int)sizeof(u64);   // ~68.5 KB -> opt in
    cudaFuncSetAttribute(neat_forward_ilp2,
                         cudaFuncAttributeMaxDynamicSharedMemorySize, smem_bytes);
    neat_forward_ilp2<<<GRID, THREADS, smem_bytes>>>(x, w, bias, resp, out);
}

// round 4
// speedup vs baseline: 1.4387x; 1.4387x over previous
#include <cuda_runtime.h>
#include <cuda_bf16.h>

#define N_IN       16
#define FANIN      16
#define N_NODES    512
#define N_OUT      64
#define BATCH      32768
#define OUT_START  (N_NODES - N_OUT)   // node 448

#define THREADS    256
#define GRID       (BATCH / THREADS)   // 128 CTAs -> 8 warps/SM -> 2 warps/SMSP

__device__ __forceinline__ float tanh_approx(float x) {
    float y; asm("tanh.approx.f32 %0, %1;" : "=f"(y) : "f"(x)); return y;
}

// Shared memory (float units):
//   [0, 8192)       : resp-folded weights w'[node][tap] = w*resp[src] (32 KB)
//   [8192, 8704)    : bias per node (2 KB)
//   [8704, 8768)    : resp for the 64 output nodes (256 B)
#define SMEM_W   0
#define SMEM_B   (N_NODES * FANIN)
#define SMEM_R   (SMEM_B + N_NODES)
#define SMEM_F32 (SMEM_R + N_OUT)

__global__ void __launch_bounds__(THREADS, 1)
neat_forward_scalar(const float* __restrict__ x,
                    const float* __restrict__ w,      // [512][16]
                    const float* __restrict__ bias,   // [512]
                    const float* __restrict__ resp,   // [512]
                    float*       __restrict__ out)    // [BATCH][64]
{
    extern __shared__ __align__(16) float sh[];
    const int tid = threadIdx.x;

    // Fold each source's response into the consumer weight:
    //   w'[i][t] = w[i][t] * resp[i + t - 16]  (identity when the source is an input).
    // The register window then carries RAW tanh values; resp is applied only
    // when storing outputs — keeping the recurrence path minimal.
    for (int i = tid; i < N_NODES * FANIN; i += THREADS) {
        const int node = i >> 4, t = i & 15;
        const int g = node + t;                        // global source index
        const float s = (g >= N_IN) ? resp[g - N_IN] : 1.0f;
        sh[SMEM_W + i] = w[i] * s;
    }
    for (int i = tid; i < N_NODES; i += THREADS) sh[SMEM_B + i] = bias[i];
    for (int i = tid; i < N_OUT;   i += THREADS) sh[SMEM_R + i] = resp[OUT_START + i];
    __syncthreads();

    const int b = blockIdx.x * THREADS + tid;          // one batch element per thread

    // Circular register window: v[g & 15] = value at global index g.
    // Node i (j = i & 15) reads v[(j+t)&15], t=0..15 (t=15 newest), writes v[j].
    float v[16];
    {
        const float4* xv = (const float4*)(x + (size_t)b * N_IN);
        #pragma unroll
        for (int q = 0; q < 4; q++) {
            float4 t = xv[q];
            v[4*q+0] = t.x; v[4*q+1] = t.y; v[4*q+2] = t.z; v[4*q+3] = t.w;
        }
    }

    float* outp = out + (size_t)b * N_OUT;

    #pragma unroll 1
    for (int g = 0; g < N_NODES / 16; g++) {
        #pragma unroll
        for (int j = 0; j < 16; j++) {
            const int node = g * 16 + j;
            const float4* wv = (const float4*)(sh + SMEM_W + node * FANIN);
            const float4 q0 = wv[0], q1 = wv[1], q2 = wv[2], q3 = wv[3];
            const float  bb = sh[SMEM_B + node];

            // Taps 0..14 depend only on node-2 and older -> their partial sum
            // (incl. bias) is OFF the serial path and overlaps node-1's tanh.
            float a0 = fmaf(v[(j + 0)  & 15], q0.x, bb);
            float a1 =      v[(j + 1)  & 15] * q0.y;
            float a2 =      v[(j + 2)  & 15] * q0.z;
            float a3 =      v[(j + 3)  & 15] * q0.w;
            a0 = fmaf(v[(j + 4)  & 15], q1.x, a0);
            a1 = fmaf(v[(j + 5)  & 15], q1.y, a1);
            a2 = fmaf(v[(j + 6)  & 15], q1.z, a2);
            a3 = fmaf(v[(j + 7)  & 15], q1.w, a3);
            a0 = fmaf(v[(j + 8)  & 15], q2.x, a0);
            a1 = fmaf(v[(j + 9)  & 15], q2.y, a1);
            a2 = fmaf(v[(j + 10) & 15], q2.z, a2);
            a3 = fmaf(v[(j + 11) & 15], q2.w, a3);
            a0 = fmaf(v[(j + 12) & 15], q3.x, a0);
            a1 = fmaf(v[(j + 13) & 15], q3.y, a1);
            a2 = fmaf(v[(j + 14) & 15], q3.z, a2);
            const float partial = (a0 + a1) + (a2 + a3);

            // Serial path per node: ONE fma + tanh.
            const float agg = fmaf(v[(j + 15) & 15], q3.w, partial);
            const float y = tanh_approx(agg);
            v[j] = y;

            if (g >= OUT_START / 16) {
                const int o = node - OUT_START;
                outp[o] = y * sh[SMEM_R + o];          // apply response off-path
            }
        }
    }
}

extern "C" void kernel_launch(void* const* d_in, const int* in_sizes, int n_in,
                              void* d_out, int out_size) {
    const float* x    = (const float*)d_in[0];   // [BATCH, 16]
    const float* w    = (const float*)d_in[1];   // [512, 16]
    const float* bias = (const float*)d_in[2];   // [512]
    const float* resp = (const float*)d_in[3];   // [512]
    // d_in[4] (src_idx) is the fixed sliding-window topology; baked into indexing.
    float* out = (float*)d_out;                  // [BATCH, 64]

    const int smem_bytes = SMEM_F32 * (int)sizeof(float);   // ~34.3 KB
    neat_forward_scalar<<<GRID, THREADS, smem_bytes>>>(x, w, bias, resp, out);
}